// round 11
// baseline (speedup 1.0000x reference)
#include <cuda_runtime.h>
#include <cuda_fp16.h>

// ---------------------------------------------------------------------------
// ESN recurrence, fp16 tensor-core, round 11.
//  = R9 compute core (2m x 4n blocking, K/8 strided, fp16 smem reduction)
//  + per-producer flags, warp-local parallel polling (lanes 0..7 watch the
//    8 producers this warp consumes; __all_sync vote; fence.acq_rel after)
//  + TRIPLE-buffered g_H: step t reads buf t%3, writes buf (t+1)%3. A CTA
//    reaches step t+2 (overwriting buf t%3) only after all 16 producers
//    showed flag >= t+1, i.e. finished step t, i.e. finished reading buf t%3.
//    -> bounded drift is provably race-free (double buffer was not).
// ---------------------------------------------------------------------------

#define TT     2048
#define BB     256
#define HH     1024
#define DD     128
#define NCTA   128
#define THREADS 512
#define KEEP0  2028
#define NLAST  20
#define KOUT   (NLAST*HH)

#define SMEM_W_BYTES   (72*4*32*16)      // 147456: [kc 72][n8p 4][lane 32] uint4
#define SMEM_RED_BYTES (8*2*8*32*8)      // 32768:  [n8l 8][mi 2][wk 8][lane 32] uint2
#define SMEM_TOTAL     (SMEM_W_BYTES + SMEM_RED_BYTES)

// ---- device globals --------------------------------------------------------
__device__ __align__(16) uint4 g_X[(size_t)TT*16*8*32];   // x frags fp16
__device__ __align__(16) uint4 g_W[16*72*4*32];           // [cta 16][kc 72][n8p 4][lane]
__device__ __align__(16) uint4 g_H[3][16][64][32];        // h frags [buf][m16][kc][lane]
__device__ float    g_hist[(size_t)NLAST*BB*HH];
__device__ unsigned g_pflag[8*16*32];                     // [group 8][producer 16], 128B apart

// ---- helpers ---------------------------------------------------------------
__device__ __forceinline__ unsigned pkh(float a, float b) {
    __half2 t = __floats2half2_rn(a, b);
    return reinterpret_cast<unsigned&>(t);
}
__device__ __forceinline__ float2 uph(unsigned u) {
    __half2 t = reinterpret_cast<__half2&>(u);
    return __half22float2(t);
}
__device__ __forceinline__ void mma16816(float* c, const uint4 a, const uint2 b) {
    asm volatile(
        "mma.sync.aligned.m16n8k16.row.col.f32.f16.f16.f32 "
        "{%0,%1,%2,%3}, {%4,%5,%6,%7}, {%8,%9}, {%0,%1,%2,%3};\n"
        : "+f"(c[0]), "+f"(c[1]), "+f"(c[2]), "+f"(c[3])
        : "r"(a.x), "r"(a.y), "r"(a.z), "r"(a.w), "r"(b.x), "r"(b.y));
}

// one kc: A frags a0 (m16g0), a1 (m16g1); B uint4 pair b0 (n8 0,1), b1 (n8 2,3)
// c layout: [mi 2][nj 4][4]
__device__ __forceinline__ void mma_kc(float* c, uint4 a0, uint4 a1, uint4 b0, uint4 b1) {
    mma16816(c + 0,  a0, make_uint2(b0.x, b0.y));
    mma16816(c + 4,  a0, make_uint2(b0.z, b0.w));
    mma16816(c + 8,  a0, make_uint2(b1.x, b1.y));
    mma16816(c + 12, a0, make_uint2(b1.z, b1.w));
    mma16816(c + 16, a1, make_uint2(b0.x, b0.y));
    mma16816(c + 20, a1, make_uint2(b0.z, b0.w));
    mma16816(c + 24, a1, make_uint2(b1.x, b1.y));
    mma16816(c + 28, a1, make_uint2(b1.z, b1.w));
}

// ---- prep kernels ----------------------------------------------------------
__global__ void prep_zero() {
    for (int i = threadIdx.x; i < 8 * 16 * 32; i += blockDim.x) g_pflag[i] = 0u;
}

// g_W[cta][kc][n8p][lane] uint4 = B frags for n8 = cta*8 + n8p*2 + {0,1}
__global__ void prep_w(const float* __restrict__ w_r, const float* __restrict__ w_in) {
    int i = blockIdx.x * blockDim.x + threadIdx.x;
    if (i >= 16 * 72 * 4 * 32) return;
    int lane = i & 31;
    int n8p  = (i >> 5) & 3;
    int kc   = (i >> 7) % 72;
    int cta  = i / (72 * 4 * 32);
    unsigned u[4];
#pragma unroll
    for (int sub = 0; sub < 2; sub++) {
        int n8 = cta * 8 + n8p * 2 + sub;
        int n  = n8 * 8 + (lane >> 2);
        int k0 = kc * 16 + (lane & 3) * 2;
        float v[4];
#pragma unroll
        for (int r = 0; r < 4; r++) {
            int k = k0 + ((r >> 1) * 8) + (r & 1);   // k0,k0+1,k0+8,k0+9
            v[r] = (k < HH) ? w_r[(size_t)k * HH + n] : w_in[(size_t)(k - HH) * HH + n];
        }
        u[2*sub + 0] = pkh(v[0], v[1]);
        u[2*sub + 1] = pkh(v[2], v[3]);
    }
    g_W[i] = make_uint4(u[0], u[1], u[2], u[3]);
}

__global__ void prep_x(const float* __restrict__ x) {
    size_t i = (size_t)blockIdx.x * blockDim.x + threadIdx.x;
    if (i >= (size_t)TT * 16 * 8 * 32) return;
    int lane = (int)(i & 31);
    int kcx  = (int)((i >> 5) & 7);
    int m16  = (int)((i >> 8) & 15);
    int t    = (int)(i >> 12);
    int b = m16 * 16 + (lane >> 2);
    int d = kcx * 16 + (lane & 3) * 2;
    const float* p0 = x + ((size_t)b * TT + t) * DD + d;
    const float* p1 = p0 + (size_t)8 * TT * DD;
    float2 a0 = *(const float2*)(p0);
    float2 a1 = *(const float2*)(p1);
    float2 a2 = *(const float2*)(p0 + 8);
    float2 a3 = *(const float2*)(p1 + 8);
    g_X[i] = make_uint4(pkh(a0.x, a0.y), pkh(a1.x, a1.y),
                        pkh(a2.x, a2.y), pkh(a3.x, a3.y));
}

// ---- main persistent kernel ------------------------------------------------
__global__ void __launch_bounds__(THREADS, 1) esn_main() {
    extern __shared__ __align__(16) unsigned char smem[];
    uint4* sW   = reinterpret_cast<uint4*>(smem);
    uint2* sred = reinterpret_cast<uint2*>(smem + SMEM_W_BYTES);

    const int tid   = threadIdx.x;
    const int lane  = tid & 31;
    const int warp  = tid >> 5;
    const int wn    = warp & 1;          // n-half: n8l 4wn..4wn+3
    const int wk    = warp >> 1;         // K-eighth 0..7 (kc = wk + 8i)
    const int cta_n = blockIdx.x & 15;
    const int cta_m = blockIdx.x >> 4;   // 8 independent groups
    const int m16g0 = 2 * cta_m;
    const int m16g1 = m16g0 + 1;

    // owned output fragment
    const int o_mi  = wk >> 2;
    const int o_nj  = wk & 3;
    const int o_n8l = 4 * wn + o_nj;
    const int o_m16 = m16g0 + o_mi;
    const int o_n8g = cta_n * 8 + o_n8l;
    const int o_kcA = o_n8g >> 1;
    const int o_half = o_n8l & 1;

    // load W tile into smem
    {
        const uint4* src = g_W + (size_t)cta_n * 72 * 4 * 32;
        for (int i = tid; i < 72 * 4 * 32; i += THREADS) sW[i] = src[i];
    }
    __syncthreads();

    unsigned* const myflag = &g_pflag[(cta_m * 16 + cta_n) * 32];
    const int watch_p = (wk + 8 * (lane & 7)) >> 2;   // producer of chunk (lane&7)
    unsigned* const watch_fp = &g_pflag[(cta_m * 16 + watch_p) * 32];
    const bool watch_active = (lane < 8) && (watch_p != cta_n);

    float hprev[4];
    int rb = 0, wb = 1;                  // t%3 and (t+1)%3, maintained by wrap

    for (int t = 0; t < TT; t++) {
        float c[32];
#pragma unroll
        for (int i = 0; i < 32; i++) c[i] = 0.f;

        // pre-wait: own x-chunk (kc = 64 + wk)
        {
            uint4 a0 = __ldg(&g_X[(((size_t)t * 16 + m16g0) * 8 + wk) * 32 + lane]);
            uint4 a1 = __ldg(&g_X[(((size_t)t * 16 + m16g1) * 8 + wk) * 32 + lane]);
            int kc = 64 + wk;
            uint4 b0 = sW[(kc * 4 + 2 * wn)     * 32 + lane];
            uint4 b1 = sW[(kc * 4 + 2 * wn + 1) * 32 + lane];
            mma_kc(c, a0, a1, b0, b1);
        }

        if (t > 0) {
            // warp-local wait: 8 producer flags polled in parallel (lanes 0..7)
            bool ready = !watch_active;
            if (!ready) {
                unsigned v;
                asm volatile("ld.relaxed.gpu.global.u32 %0, [%1];"
                             : "=r"(v) : "l"(watch_fp) : "memory");
                ready = (v >= (unsigned)t);
            }
            while (!__all_sync(0xffffffffu, ready)) {
                if (!ready) {
                    unsigned v;
                    asm volatile("ld.relaxed.gpu.global.u32 %0, [%1];"
                                 : "=r"(v) : "l"(watch_fp) : "memory");
                    ready = (v >= (unsigned)t);
                }
            }
            asm volatile("fence.acq_rel.gpu;" ::: "memory");

            const uint4* A0 = &g_H[rb][m16g0][wk][lane];   // stride 8*32 per chunk
            const uint4* A1 = &g_H[rb][m16g1][wk][lane];
            uint4 ra[2][2];
            ra[0][0] = __ldcg(A0);                 ra[0][1] = __ldcg(A1);
            ra[1][0] = __ldcg(A0 + 8 * 32);        ra[1][1] = __ldcg(A1 + 8 * 32);
#pragma unroll
            for (int i = 0; i < 8; i++) {
                uint4 a0 = ra[i & 1][0];
                uint4 a1 = ra[i & 1][1];
                if (i + 2 < 8) {
                    ra[i & 1][0] = __ldcg(A0 + (size_t)(i + 2) * 8 * 32);
                    ra[i & 1][1] = __ldcg(A1 + (size_t)(i + 2) * 8 * 32);
                }
                int kc = wk + 8 * i;
                uint4 b0 = sW[(kc * 4 + 2 * wn)     * 32 + lane];
                uint4 b1 = sW[(kc * 4 + 2 * wn + 1) * 32 + lane];
                mma_kc(c, a0, a1, b0, b1);
            }
        }

        // write fp16-packed partials for the 7 fragments we don't own
#pragma unroll
        for (int mi = 0; mi < 2; mi++) {
#pragma unroll
            for (int nj = 0; nj < 4; nj++) {
                if (mi == o_mi && nj == o_nj) continue;
                int n8l = 4 * wn + nj;
                const float* p = c + (mi * 16 + nj * 4);
                sred[(((n8l * 2 + mi) * 8) + wk) * 32 + lane] =
                    make_uint2(pkh(p[0], p[1]), pkh(p[2], p[3]));
            }
        }
        __syncthreads();

        // owner epilogue: own fp32 partial + 7 foreign fp16 partials
        float fin[4];
        {
            const float* p = c + (o_mi * 16 + o_nj * 4);
            fin[0] = p[0]; fin[1] = p[1]; fin[2] = p[2]; fin[3] = p[3];
            const uint2* rbase = &sred[((o_n8l * 2 + o_mi) * 8) * 32 + lane];
#pragma unroll
            for (int w = 0; w < 8; w++) {
                if (w == wk) continue;
                uint2 v = rbase[w * 32];
                float2 lo = uph(v.x), hi = uph(v.y);
                fin[0] += lo.x; fin[1] += lo.y; fin[2] += hi.x; fin[3] += hi.y;
            }
        }

        float hv[4];
        if (t == 0) {
#pragma unroll
            for (int i = 0; i < 4; i++) hv[i] = tanhf(fin[i]);
        } else {
#pragma unroll
            for (int i = 0; i < 4; i++) hv[i] = 0.1f * hprev[i] + 0.9f * tanhf(fin[i]);
        }
#pragma unroll
        for (int i = 0; i < 4; i++) hprev[i] = hv[i];

        // store owned h fragment half (uint2) into buf wb
        {
            uint2 nh = make_uint2(pkh(hv[0], hv[1]), pkh(hv[2], hv[3]));
            char* dst = (char*)&g_H[wb][o_m16][o_kcA][lane] + o_half * 8;
            asm volatile("st.global.cg.v2.u32 [%0], {%1, %2};"
                         :: "l"(dst), "r"(nh.x), "r"(nh.y) : "memory");
        }

        // all stores done -> bump this CTA's producer flag
        if (t < TT - 1) {
            __syncthreads();
            if (tid == 0)
                asm volatile("red.release.gpu.global.add.u32 [%0], %1;"
                             :: "l"(myflag), "r"(1u) : "memory");
        }

        if (t >= KEEP0) {
            int r0 = o_m16 * 16 + (lane >> 2);
            int cb = o_n8g * 8 + (lane & 3) * 2;
            size_t base = (size_t)(t - KEEP0) * BB * HH;
            *(float2*)&g_hist[base + (size_t)(r0)     * HH + cb] = make_float2(hv[0], hv[1]);
            *(float2*)&g_hist[base + (size_t)(r0 + 8) * HH + cb] = make_float2(hv[2], hv[3]);
        }

        rb = wb;
        wb = wb + 1; if (wb == 3) wb = 0;
    }
}

// ---- readout ---------------------------------------------------------------
__global__ void readout(const float* __restrict__ lw, const float* __restrict__ lb,
                        float* __restrict__ out) {
    int b    = blockIdx.x;
    int warp = threadIdx.x >> 5;
    int lane = threadIdx.x & 31;
    int o0   = warp * 4;
    float a0 = 0.f, a1 = 0.f, a2 = 0.f, a3 = 0.f;
    for (int k = lane; k < KOUT; k += 32) {
        int s = k >> 10, j = k & (HH - 1);
        float hval = g_hist[(size_t)s * BB * HH + (size_t)b * HH + j];
        a0 += hval * __ldg(&lw[(size_t)(o0 + 0) * KOUT + k]);
        a1 += hval * __ldg(&lw[(size_t)(o0 + 1) * KOUT + k]);
        a2 += hval * __ldg(&lw[(size_t)(o0 + 2) * KOUT + k]);
        a3 += hval * __ldg(&lw[(size_t)(o0 + 3) * KOUT + k]);
    }
#pragma unroll
    for (int off = 16; off > 0; off >>= 1) {
        a0 += __shfl_down_sync(0xffffffffu, a0, off);
        a1 += __shfl_down_sync(0xffffffffu, a1, off);
        a2 += __shfl_down_sync(0xffffffffu, a2, off);
        a3 += __shfl_down_sync(0xffffffffu, a3, off);
    }
    if (lane == 0) {
        out[b * 32 + o0 + 0] = a0 + lb[o0 + 0];
        out[b * 32 + o0 + 1] = a1 + lb[o0 + 1];
        out[b * 32 + o0 + 2] = a2 + lb[o0 + 2];
        out[b * 32 + o0 + 3] = a3 + lb[o0 + 3];
    }
}

// ---- launch ----------------------------------------------------------------
extern "C" void kernel_launch(void* const* d_in, const int* in_sizes, int n_in,
                              void* d_out, int out_size) {
    const float* x    = (const float*)d_in[0];
    const float* w_in = (const float*)d_in[1];
    const float* w_r  = (const float*)d_in[2];
    const float* lw   = (const float*)d_in[3];
    const float* lb   = (const float*)d_in[4];
    float* out = (float*)d_out;

    cudaFuncSetAttribute(esn_main, cudaFuncAttributeMaxDynamicSharedMemorySize, SMEM_TOTAL);

    prep_zero<<<1, 256>>>();
    prep_w<<<(16 * 72 * 4 * 32 + 255) / 256, 256>>>(w_r, w_in);
    prep_x<<<(int)(((size_t)TT * 16 * 8 * 32) / 256), 256>>>(x);
    esn_main<<<NCTA, THREADS, SMEM_TOTAL>>>();
    readout<<<BB, 256>>>(lw, lb, out);
}